// round 1
// baseline (speedup 1.0000x reference)
#include <cuda_runtime.h>
#include <math.h>

#define BATCH 16
#define ZD 256
#define OC 256
#define IC 128
#define FANIN (IC*9)          // 1152
#define NTOT (OC*FANIN)       // 294912
#define HW 64

// Scratch (device globals — no allocation APIs)
__device__ float g_dw[BATCH*NTOT];   // delta_w, layout [b][n]
__device__ float g_w[BATCH*NTOT];    // final per-sample weights, layout [b][oc][cin][3][3]

// ---------------------------------------------------------------------------
// Kernel A: delta[b][n] = sum_k z[b][k] * head_w[n][k]
// 128 threads, N_TILE=512, K_TILE=8. Thread tile: 8 b x 8 n.
// ---------------------------------------------------------------------------
__global__ void __launch_bounds__(128) gemm_delta(const float* __restrict__ z,
                                                  const float* __restrict__ hw)
{
    __shared__ float z_s[BATCH][ZD];       // 16 KB, broadcast reads
    __shared__ float hw_s[8][516];         // [k][n] transposed, pad 4

    const int tid = threadIdx.x;
    const int n0  = blockIdx.x * 512;

    // load all of z once (coalesced float4)
    {
        const float4* zg = (const float4*)z;
        float4* zs = (float4*)&z_s[0][0];
        #pragma unroll
        for (int f = tid; f < BATCH*ZD/4; f += 128) zs[f] = zg[f];
    }

    const int bg  = tid >> 6;    // 0..1  -> b range bg*8..bg*8+7
    const int nth = tid & 63;    // 0..63 -> n = n0 + j*64 + nth

    float acc[8][8];
    #pragma unroll
    for (int i = 0; i < 8; i++)
        #pragma unroll
        for (int j = 0; j < 8; j++) acc[i][j] = 0.f;

    for (int kt = 0; kt < ZD/8; kt++) {
        __syncthreads();
        // stage head_w tile [512 rows][8 k] transposed into hw_s[k][n]
        #pragma unroll
        for (int f = tid; f < 1024; f += 128) {
            int row = f >> 1;
            int c4  = f & 1;
            float4 v = *(const float4*)&hw[(size_t)(n0 + row)*ZD + kt*8 + c4*4];
            hw_s[c4*4+0][row] = v.x;
            hw_s[c4*4+1][row] = v.y;
            hw_s[c4*4+2][row] = v.z;
            hw_s[c4*4+3][row] = v.w;
        }
        __syncthreads();

        #pragma unroll
        for (int k = 0; k < 8; k++) {
            float zr[8], hr[8];
            #pragma unroll
            for (int bi = 0; bi < 8; bi++) zr[bi] = z_s[bg*8+bi][kt*8+k];
            #pragma unroll
            for (int j = 0; j < 8; j++)  hr[j] = hw_s[k][j*64 + nth];
            #pragma unroll
            for (int bi = 0; bi < 8; bi++)
                #pragma unroll
                for (int j = 0; j < 8; j++)
                    acc[bi][j] = fmaf(zr[bi], hr[j], acc[bi][j]);
        }
    }

    #pragma unroll
    for (int bi = 0; bi < 8; bi++)
        #pragma unroll
        for (int j = 0; j < 8; j++)
            g_dw[(size_t)(bg*8+bi)*NTOT + n0 + j*64 + nth] = acc[bi][j];
}

// ---------------------------------------------------------------------------
// Kernel B: per (b, oc): standardize delta over 1152, build final weight.
// w = (base + (dw-mu)*rsqrt(var+eps)*sqrt(2/fanin)) / sqrt(2)
// ---------------------------------------------------------------------------
__global__ void __launch_bounds__(128) build_w(const float* __restrict__ base)
{
    const int b  = blockIdx.x >> 8;
    const int oc = blockIdx.x & 255;
    const int tid = threadIdx.x;

    const float* dwp = &g_dw[(size_t)b*NTOT + oc*FANIN];

    float v[9];
    float s = 0.f, sq = 0.f;
    #pragma unroll
    for (int t = 0; t < 9; t++) {
        v[t] = dwp[tid + t*128];
        s  += v[t];
        sq += v[t]*v[t];
    }
    #pragma unroll
    for (int off = 16; off; off >>= 1) {
        s  += __shfl_xor_sync(0xffffffffu, s,  off);
        sq += __shfl_xor_sync(0xffffffffu, sq, off);
    }
    __shared__ float ss[4], ssq[4];
    const int wid = tid >> 5;
    if ((tid & 31) == 0) { ss[wid] = s; ssq[wid] = sq; }
    __syncthreads();
    s  = ss[0] + ss[1] + ss[2] + ss[3];
    sq = ssq[0] + ssq[1] + ssq[2] + ssq[3];

    const float inv_n = 1.0f / (float)FANIN;
    float mu  = s * inv_n;
    float var = sq * inv_n - mu*mu;
    float rs  = rsqrtf(var + 1e-5f);
    const float inv_sqrt2 = 0.70710678118654752440f;
    float c1 = rs * sqrtf(2.0f / (float)FANIN) * inv_sqrt2;

    const float* bw   = &base[(size_t)oc*FANIN];
    float*       wout = &g_w[(size_t)b*NTOT + oc*FANIN];
    #pragma unroll
    for (int t = 0; t < 9; t++) {
        int i = tid + t*128;
        wout[i] = bw[i]*inv_sqrt2 + (v[t] - mu)*c1;
    }
}

// ---------------------------------------------------------------------------
// Kernel C: per-sample 3x3 conv, pad=1.
// Grid: (4 spatial tiles of 32x32, 32 oc-tiles of 8, 16 batches). 128 threads.
// Thread micro-tile: 2(y) x 4(x) spatial x 8 oc = 64 accumulators.
// ---------------------------------------------------------------------------
__global__ void __launch_bounds__(128) conv3x3(const float* __restrict__ x,
                                               float* __restrict__ out)
{
    __shared__ float x_s[8][34][35];   // 38.1 KB, row-padded -> conflict-free
    __shared__ float w_s[8][8][9];     // [oc][cin][tap], broadcast reads

    const int tid = threadIdx.x;
    const int sx  = (blockIdx.x & 1) * 32;
    const int sy  = (blockIdx.x >> 1) * 32;
    const int oc0 = blockIdx.y * 8;
    const int b   = blockIdx.z;

    const int tx = (tid & 7) * 4;   // 0..28 step 4
    const int ty = (tid >> 3) * 2;  // 0..30 step 2

    float acc[8][2][4];
    #pragma unroll
    for (int o = 0; o < 8; o++)
        #pragma unroll
        for (int i = 0; i < 2; i++)
            #pragma unroll
            for (int j = 0; j < 4; j++) acc[o][i][j] = 0.f;

    const float* xb = x + (size_t)b*IC*HW*HW;
    const float* wb = g_w + (size_t)b*NTOT + (size_t)oc0*FANIN;

    for (int cc = 0; cc < IC/8; cc++) {
        __syncthreads();
        // stage x chunk: 8 cin x 34x34 with halo + zero pad
        for (int idx = tid; idx < 8*1156; idx += 128) {
            int c   = idx / 1156;
            int rem = idx - c*1156;
            int iy  = rem / 34;
            int ix  = rem - iy*34;
            int gy  = sy + iy - 1;
            int gx  = sx + ix - 1;
            float val = 0.f;
            if (gy >= 0 && gy < HW && gx >= 0 && gx < HW)
                val = xb[((size_t)(cc*8 + c)*HW + gy)*HW + gx];
            x_s[c][iy][ix] = val;
        }
        // stage w chunk: 8 oc x 8 cin x 9
        for (int idx = tid; idx < 576; idx += 128) {
            int o   = idx / 72;
            int rem = idx - o*72;
            int c   = rem / 9;
            int t   = rem - c*9;
            w_s[o][c][t] = wb[(size_t)o*FANIN + cc*72 + rem];
        }
        __syncthreads();

        #pragma unroll
        for (int c = 0; c < 8; c++) {
            #pragma unroll
            for (int r = 0; r < 3; r++) {
                #pragma unroll
                for (int s = 0; s < 3; s++) {
                    float xv[2][4];
                    #pragma unroll
                    for (int i = 0; i < 2; i++)
                        #pragma unroll
                        for (int j = 0; j < 4; j++)
                            xv[i][j] = x_s[c][ty + i + r][tx + j + s];
                    #pragma unroll
                    for (int o = 0; o < 8; o++) {
                        float wr = w_s[o][c][r*3 + s];
                        #pragma unroll
                        for (int i = 0; i < 2; i++)
                            #pragma unroll
                            for (int j = 0; j < 4; j++)
                                acc[o][i][j] = fmaf(xv[i][j], wr, acc[o][i][j]);
                    }
                }
            }
        }
    }

    // epilogue: vectorized stores (ox aligned to 16B)
    #pragma unroll
    for (int o = 0; o < 8; o++) {
        #pragma unroll
        for (int i = 0; i < 2; i++) {
            int oy = sy + ty + i;
            int ox = sx + tx;
            float4 v = make_float4(acc[o][i][0], acc[o][i][1], acc[o][i][2], acc[o][i][3]);
            *(float4*)&out[(((size_t)b*OC + oc0 + o)*HW + oy)*HW + ox] = v;
        }
    }
}

// ---------------------------------------------------------------------------
extern "C" void kernel_launch(void* const* d_in, const int* in_sizes, int n_in,
                              void* d_out, int out_size)
{
    const float* x    = (const float*)d_in[0];  // [16,128,64,64]
    const float* z    = (const float*)d_in[1];  // [16,256]
    const float* bw   = (const float*)d_in[2];  // [256,128,3,3]
    const float* hw   = (const float*)d_in[3];  // [294912,256]
    float*       out  = (float*)d_out;          // [16,256,64,64]

    gemm_delta<<<NTOT/512, 128>>>(z, hw);
    build_w<<<BATCH*OC, 128>>>(bw);
    conv3x3<<<dim3(4, OC/8, BATCH), 128>>>(x, out);
}

// round 3
// speedup vs baseline: 2.7062x; 2.7062x over previous
#include <cuda_runtime.h>
#include <cuda_bf16.h>
#include <cstdint>
#include <math.h>

#define BATCH 16
#define ZD 256
#define OC 256
#define IC 128
#define FANIN (IC*9)          // 1152
#define NTOT (OC*FANIN)       // 294912
#define HW 64

// ---------------- device scratch (no allocation APIs) ----------------
__device__ float g_dw[BATCH*NTOT];                    // delta_w [b][n]
__device__ __nv_bfloat16 g_whi[BATCH*OC*9*IC];        // weights hi, [b][oc][tap][cin]
__device__ __nv_bfloat16 g_wlo[BATCH*OC*9*IC];        // weights lo

// mma.sync bf16 (sm_80-era PTX — valid on plain compute_103 virtual arch)
__device__ __forceinline__ void mma16816(float* d, const uint32_t* a,
                                         uint32_t b0, uint32_t b1) {
    asm volatile(
        "mma.sync.aligned.m16n8k16.row.col.f32.bf16.bf16.f32 "
        "{%0,%1,%2,%3}, {%4,%5,%6,%7}, {%8,%9}, {%0,%1,%2,%3};"
        : "+f"(d[0]), "+f"(d[1]), "+f"(d[2]), "+f"(d[3])
        : "r"(a[0]), "r"(a[1]), "r"(a[2]), "r"(a[3]), "r"(b0), "r"(b1));
}

// ---------------------------------------------------------------------------
// Kernel A: delta[b][n] = sum_k z[b][k] * head_w[n][k]
// N_TILE=256 -> 1152 CTAs (was 576; occ was grid-limited at 20.8%)
// ---------------------------------------------------------------------------
__global__ void __launch_bounds__(128) gemm_delta(const float* __restrict__ z,
                                                  const float* __restrict__ hw)
{
    __shared__ float z_s[BATCH][ZD];
    __shared__ float hw_s[8][260];

    const int tid = threadIdx.x;
    const int n0  = blockIdx.x * 256;

    {
        const float4* zg = (const float4*)z;
        float4* zs = (float4*)&z_s[0][0];
        #pragma unroll
        for (int f = tid; f < BATCH*ZD/4; f += 128) zs[f] = zg[f];
    }

    const int bg  = tid >> 6;     // 0..1 -> 8 batches each
    const int nth = tid & 63;

    float acc[8][4];
    #pragma unroll
    for (int i = 0; i < 8; i++)
        #pragma unroll
        for (int j = 0; j < 4; j++) acc[i][j] = 0.f;

    for (int kt = 0; kt < ZD/8; kt++) {
        __syncthreads();
        #pragma unroll
        for (int f = tid; f < 512; f += 128) {
            int row = f >> 1;
            int c4  = f & 1;
            float4 v = *(const float4*)&hw[(size_t)(n0 + row)*ZD + kt*8 + c4*4];
            hw_s[c4*4+0][row] = v.x;
            hw_s[c4*4+1][row] = v.y;
            hw_s[c4*4+2][row] = v.z;
            hw_s[c4*4+3][row] = v.w;
        }
        __syncthreads();

        #pragma unroll
        for (int k = 0; k < 8; k++) {
            float zr[8], hr[4];
            #pragma unroll
            for (int bi = 0; bi < 8; bi++) zr[bi] = z_s[bg*8+bi][kt*8+k];
            #pragma unroll
            for (int j = 0; j < 4; j++)  hr[j] = hw_s[k][j*64 + nth];
            #pragma unroll
            for (int bi = 0; bi < 8; bi++)
                #pragma unroll
                for (int j = 0; j < 4; j++)
                    acc[bi][j] = fmaf(zr[bi], hr[j], acc[bi][j]);
        }
    }

    #pragma unroll
    for (int bi = 0; bi < 8; bi++)
        #pragma unroll
        for (int j = 0; j < 4; j++)
            g_dw[(size_t)(bg*8+bi)*NTOT + n0 + j*64 + nth] = acc[bi][j];
}

// ---------------------------------------------------------------------------
// Kernel B: standardize + build weights, emit bf16 hi/lo, [b][oc][tap][cin]
// ---------------------------------------------------------------------------
__global__ void __launch_bounds__(128) build_w(const float* __restrict__ base)
{
    const int b  = blockIdx.x >> 8;
    const int oc = blockIdx.x & 255;
    const int tid = threadIdx.x;

    const float* dwp = &g_dw[(size_t)b*NTOT + oc*FANIN];

    float v[9];
    float s = 0.f, sq = 0.f;
    #pragma unroll
    for (int t = 0; t < 9; t++) {
        v[t] = dwp[tid + t*128];
        s  += v[t];
        sq += v[t]*v[t];
    }
    #pragma unroll
    for (int off = 16; off; off >>= 1) {
        s  += __shfl_xor_sync(0xffffffffu, s,  off);
        sq += __shfl_xor_sync(0xffffffffu, sq, off);
    }
    __shared__ float ss[4], ssq[4];
    const int wid = tid >> 5;
    if ((tid & 31) == 0) { ss[wid] = s; ssq[wid] = sq; }
    __syncthreads();
    s  = ss[0] + ss[1] + ss[2] + ss[3];
    sq = ssq[0] + ssq[1] + ssq[2] + ssq[3];

    const float inv_n = 1.0f / (float)FANIN;
    float mu  = s * inv_n;
    float var = sq * inv_n - mu*mu;
    float rs  = rsqrtf(var + 1e-5f);
    const float inv_sqrt2 = 0.70710678118654752440f;
    float c1 = rs * sqrtf(2.0f / (float)FANIN) * inv_sqrt2;

    const float* bw = &base[(size_t)oc*FANIN];
    __nv_bfloat16* whi = &g_whi[(size_t)(b*OC + oc)*9*IC];
    __nv_bfloat16* wlo = &g_wlo[(size_t)(b*OC + oc)*9*IC];
    #pragma unroll
    for (int t = 0; t < 9; t++) {
        int i = tid + t*128;           // i = cin*9 + tap
        int cin = i / 9, tap = i - cin*9;
        float w = bw[i]*inv_sqrt2 + (v[t] - mu)*c1;
        __nv_bfloat16 hi = __float2bfloat16(w);
        __nv_bfloat16 lo = __float2bfloat16(w - __bfloat162float(hi));
        whi[tap*IC + cin] = hi;
        wlo[tap*IC + cin] = lo;
    }
}

// ---------------------------------------------------------------------------
// Kernel C: implicit-GEMM conv via mma.sync bf16 (hi/lo 3-pass, fp32 accum).
// CTA = (4 y-rows, 128-oc tile, b). 512 threads = 16 warps.
// Warp (w): mw=w&3 -> 32-oc slice; yl=w>>2 -> one y-row of 64 x.
// ---------------------------------------------------------------------------
#define XS_STRIDE 144                  // bytes per (y,x) row of 64 cin bf16 (+16B pad)
#define XS_BYTES  (6*66*XS_STRIDE)     // 57024
#define SM_A_HI   0                    // 128 oc x 144B = 18432
#define SM_A_LO   18432
#define SM_XS_HI  36864
#define SM_XS_LO  (SM_XS_HI + XS_BYTES)     // 93888
#define CONV_SMEM (SM_XS_LO + XS_BYTES)     // 150912

__global__ void __launch_bounds__(512, 1) conv_mma(const float* __restrict__ x,
                                                   float* __restrict__ out)
{
    extern __shared__ char smem[];
    const int tid  = threadIdx.x;
    const int wid  = tid >> 5;
    const int lane = tid & 31;
    const int y0   = blockIdx.x * 4;
    const int oc0  = blockIdx.y * 128;
    const int b    = blockIdx.z;

    const int mw = wid & 3;       // oc quarter
    const int yl = wid >> 2;      // local y row
    const int qr = lane >> 2;     // 0..7
    const int qc = lane & 3;      // 0..3

    float acc[2][8][4];
    #pragma unroll
    for (int mf = 0; mf < 2; mf++)
        #pragma unroll
        for (int nf = 0; nf < 8; nf++)
            #pragma unroll
            for (int q = 0; q < 4; q++) acc[mf][nf][q] = 0.f;

    // zero xs once (halo pads at x'=0/65 and OOB y rows stay zero)
    for (int i = tid; i < (2*XS_BYTES)/16; i += 512)
        *(uint4*)(smem + SM_XS_HI + i*16) = make_uint4(0u,0u,0u,0u);
    __syncthreads();

    for (int ch = 0; ch < 2; ch++) {
        // ---- stage x chunk: [6 y][66 x][64 cin] bf16 hi/lo, channels-last ----
        for (int i = tid; i < 6*64*16; i += 512) {
            int ys  = i >> 10;
            int rem = i & 1023;
            int c   = rem >> 4;
            int x4  = rem & 15;
            int gy  = y0 - 1 + ys;
            if (gy >= 0 && gy < HW) {
                const float4 v = *(const float4*)
                    &x[(((size_t)(b*IC + ch*64 + c)*HW) + gy)*HW + x4*4];
                float f[4] = {v.x, v.y, v.z, v.w};
                #pragma unroll
                for (int q = 0; q < 4; q++) {
                    __nv_bfloat16 hi = __float2bfloat16(f[q]);
                    __nv_bfloat16 lo = __float2bfloat16(f[q] - __bfloat162float(hi));
                    int off = (ys*66 + x4*4 + q + 1)*XS_STRIDE + c*2;
                    *(__nv_bfloat16*)(smem + SM_XS_HI + off) = hi;
                    *(__nv_bfloat16*)(smem + SM_XS_LO + off) = lo;
                }
            }
        }
        __syncthreads();

        for (int tap = 0; tap < 9; tap++) {
            const int r = tap / 3, s = tap - r*3;

            // ---- stage A: [128 oc][64 cin] hi/lo (rows padded to 144B) ----
            {
                const size_t abase = ((size_t)((b*OC + oc0)*9 + tap))*IC + (size_t)ch*64;
                for (int i = tid; i < 1024; i += 512) {
                    int row = i >> 3, j = i & 7;
                    size_t off8 = (abase + (size_t)row*(9*IC)) / 8 + j;   // uint4 index
                    uint4 vh = ((const uint4*)g_whi)[off8];
                    uint4 vl = ((const uint4*)g_wlo)[off8];
                    *(uint4*)(smem + SM_A_HI + row*XS_STRIDE + j*16) = vh;
                    *(uint4*)(smem + SM_A_LO + row*XS_STRIDE + j*16) = vl;
                }
            }
            __syncthreads();

            // ---- compute: K=64 over this (ch,tap) ----
            {
                const int a_row0 = (mw*32 + qr)*XS_STRIDE + qc*4;   // mf stride 16*144
                const int bbase  = ((yl + r)*66 + s + qr)*XS_STRIDE + qc*4;

                #pragma unroll
                for (int ks = 0; ks < 4; ks++) {
                    const int kb = ks*32;     // byte offset of k-step
                    uint32_t ah[2][4], al[2][4];
                    #pragma unroll
                    for (int mf = 0; mf < 2; mf++) {
                        const int ar = a_row0 + mf*(16*XS_STRIDE) + kb;
                        ah[mf][0] = *(const uint32_t*)(smem + SM_A_HI + ar);
                        ah[mf][1] = *(const uint32_t*)(smem + SM_A_HI + ar + 8*XS_STRIDE);
                        ah[mf][2] = *(const uint32_t*)(smem + SM_A_HI + ar + 16);
                        ah[mf][3] = *(const uint32_t*)(smem + SM_A_HI + ar + 8*XS_STRIDE + 16);
                        al[mf][0] = *(const uint32_t*)(smem + SM_A_LO + ar);
                        al[mf][1] = *(const uint32_t*)(smem + SM_A_LO + ar + 8*XS_STRIDE);
                        al[mf][2] = *(const uint32_t*)(smem + SM_A_LO + ar + 16);
                        al[mf][3] = *(const uint32_t*)(smem + SM_A_LO + ar + 8*XS_STRIDE + 16);
                    }
                    #pragma unroll
                    for (int nf = 0; nf < 8; nf++) {
                        const int ba = bbase + nf*(8*XS_STRIDE) + kb;
                        uint32_t bh0 = *(const uint32_t*)(smem + SM_XS_HI + ba);
                        uint32_t bh1 = *(const uint32_t*)(smem + SM_XS_HI + ba + 16);
                        uint32_t bl0 = *(const uint32_t*)(smem + SM_XS_LO + ba);
                        uint32_t bl1 = *(const uint32_t*)(smem + SM_XS_LO + ba + 16);
                        #pragma unroll
                        for (int mf = 0; mf < 2; mf++) {
                            mma16816(acc[mf][nf], ah[mf], bh0, bh1);
                            mma16816(acc[mf][nf], ah[mf], bl0, bl1);
                            mma16816(acc[mf][nf], al[mf], bh0, bh1);
                        }
                    }
                }
            }
            __syncthreads();   // protect A (and xs on last tap) before overwrite
        }
    }

    // ---- epilogue: d-frag -> gmem (float2 stores) ----
    const int y = y0 + yl;
    #pragma unroll
    for (int mf = 0; mf < 2; mf++) {
        const int oc = oc0 + mw*32 + mf*16 + qr;
        float* op0 = out + (((size_t)(b*OC + oc    )*HW) + y)*HW;
        float* op1 = out + (((size_t)(b*OC + oc + 8)*HW) + y)*HW;
        #pragma unroll
        for (int nf = 0; nf < 8; nf++) {
            const int xp = nf*8 + qc*2;
            *(float2*)&op0[xp] = make_float2(acc[mf][nf][0], acc[mf][nf][1]);
            *(float2*)&op1[xp] = make_float2(acc[mf][nf][2], acc[mf][nf][3]);
        }
    }
}

// ---------------------------------------------------------------------------
extern "C" void kernel_launch(void* const* d_in, const int* in_sizes, int n_in,
                              void* d_out, int out_size)
{
    const float* x    = (const float*)d_in[0];  // [16,128,64,64]
    const float* z    = (const float*)d_in[1];  // [16,256]
    const float* bw   = (const float*)d_in[2];  // [256,128,3,3]
    const float* hw   = (const float*)d_in[3];  // [294912,256]
    float*       out  = (float*)d_out;          // [16,256,64,64]

    static bool attr_set = false;
    if (!attr_set) {
        cudaFuncSetAttribute(conv_mma, cudaFuncAttributeMaxDynamicSharedMemorySize, CONV_SMEM);
        attr_set = true;
    }

    gemm_delta<<<NTOT/256, 128>>>(z, hw);
    build_w<<<BATCH*OC, 128>>>(bw);
    conv_mma<<<dim3(16, 2, BATCH), 512, CONV_SMEM>>>(x, out);
}